// round 1
// baseline (speedup 1.0000x reference)
#include <cuda_runtime.h>

#define BB 32
#define CC 512
#define QQ 128
#define DD 768
#define NEGV (-1e30f)
#define FLOOR_F (-3.402823466e38f)

// ---------------- scratch (device globals; no allocation allowed) ----------
__device__ float g_S[BB * CC * QQ];        // similarity, 8 MB
__device__ float g_a[BB * CC];             // dot(c, w1)
__device__ float g_bq[BB * QQ];            // dot(q, w2)
__device__ float g_Smax[BB * CC];          // max over q of S
__device__ float g_pmax[4 * BB * QQ];      // partial column max (over c-chunks)
__device__ float g_psum[4 * BB * QQ];      // partial column sum
__device__ float g_colmax[BB * QQ];        // final column max (masked S)
__device__ float g_colinv[BB * QQ];        // 1 / column sum
__device__ float g_cdash[BB * DD];         // c_dash per (b, d)

// ---------------- K1: row dots a[b,c] = c.w1, bq[b,q] = q.w2 ---------------
__global__ void k_rowdots(const float* __restrict__ cont,
                          const float* __restrict__ ques,
                          const float* __restrict__ SW) {
    int warp = (blockIdx.x * blockDim.x + threadIdx.x) >> 5;
    int lane = threadIdx.x & 31;
    const float* src;
    const float* w;
    float* dst;
    if (warp < BB * CC) {
        src = cont + warp * DD;
        w = SW;
        dst = g_a + warp;
    } else {
        int r = warp - BB * CC;
        if (r >= BB * QQ) return;
        src = ques + r * DD;
        w = SW + DD;
        dst = g_bq + r;
    }
    float acc = 0.f;
#pragma unroll
    for (int i = 0; i < 6; i++) {
        int k4 = lane + 32 * i;  // float4 index, covers 192 float4 = 768 floats
        float4 x = reinterpret_cast<const float4*>(src)[k4];
        float4 ww = reinterpret_cast<const float4*>(w)[k4];
        acc += x.x * ww.x + x.y * ww.y + x.z * ww.z + x.w * ww.w;
    }
#pragma unroll
    for (int o = 16; o; o >>= 1) acc += __shfl_xor_sync(0xffffffffu, acc, o);
    if (lane == 0) *dst = acc;
}

// ---------------- K2: similarity GEMM: S = a + bq + (c*w3) @ q^T -----------
// per batch: M=C=512 (tiles of 64), N=Q=128 (full), K=D=768
// block 256 threads, thread frag 4(M) x 8(N). Epilogue also writes row max
// over the FULL q range (N tile covers all Q) -> g_Smax.
__global__ void __launch_bounds__(256) k_sim(const float* __restrict__ cont,
                                             const float* __restrict__ ques,
                                             const float* __restrict__ SW) {
    const int KT = 16;
    __shared__ float As[KT][68];       // As[k][c], padded
    __shared__ float Bs[QQ][KT + 1];   // Bs[q][k], padded

    int b = blockIdx.z;
    int c0 = blockIdx.x * 64;
    int t = threadIdx.x;
    int tx = t & 15, ty = t >> 4;
    const float* w3 = SW + 2 * DD;

    float acc[4][8];
#pragma unroll
    for (int i = 0; i < 4; i++)
#pragma unroll
        for (int j = 0; j < 8; j++) acc[i][j] = 0.f;

    const float* cbase = cont + (b * CC + c0) * DD;
    const float* qbase = ques + (b * QQ) * DD;

    for (int k0 = 0; k0 < DD; k0 += KT) {
        // A tile: 64 c x 16 k = 256 float4, one per thread
        {
            int c = t >> 2, k4 = t & 3;
            float4 x = *reinterpret_cast<const float4*>(cbase + c * DD + k0 + k4 * 4);
            float4 ww = *reinterpret_cast<const float4*>(w3 + k0 + k4 * 4);
            As[k4 * 4 + 0][c] = x.x * ww.x;
            As[k4 * 4 + 1][c] = x.y * ww.y;
            As[k4 * 4 + 2][c] = x.z * ww.z;
            As[k4 * 4 + 3][c] = x.w * ww.w;
        }
        // B tile: 128 q x 16 k = 512 float4, two per thread
#pragma unroll
        for (int r = 0; r < 2; r++) {
            int f = t + 256 * r;
            int q = f >> 2, k4 = f & 3;
            float4 x = *reinterpret_cast<const float4*>(qbase + q * DD + k0 + k4 * 4);
            Bs[q][k4 * 4 + 0] = x.x;
            Bs[q][k4 * 4 + 1] = x.y;
            Bs[q][k4 * 4 + 2] = x.z;
            Bs[q][k4 * 4 + 3] = x.w;
        }
        __syncthreads();
#pragma unroll
        for (int k = 0; k < KT; k++) {
            float4 a4 = *reinterpret_cast<const float4*>(&As[k][ty * 4]);
            float av[4] = {a4.x, a4.y, a4.z, a4.w};
            float bv[8];
#pragma unroll
            for (int j = 0; j < 8; j++) bv[j] = Bs[tx + 16 * j][k];
#pragma unroll
            for (int i = 0; i < 4; i++)
#pragma unroll
                for (int j = 0; j < 8; j++) acc[i][j] += av[i] * bv[j];
        }
        __syncthreads();
    }

    // epilogue: add a + bq, store S, fused row-max over all Q
    float bqv[8];
#pragma unroll
    for (int j = 0; j < 8; j++) bqv[j] = g_bq[b * QQ + tx + 16 * j];

#pragma unroll
    for (int i = 0; i < 4; i++) {
        int c = c0 + ty * 4 + i;
        float av = g_a[b * CC + c];
        float rowm = FLOOR_F;
        float* Srow = g_S + (b * CC + c) * QQ;
#pragma unroll
        for (int j = 0; j < 8; j++) {
            int q = tx + 16 * j;
            float s = acc[i][j] + av + bqv[j];
            Srow[q] = s;
            rowm = fmaxf(rowm, s);
        }
#pragma unroll
        for (int o = 8; o; o >>= 1)
            rowm = fmaxf(rowm, __shfl_xor_sync(0xffffffffu, rowm, o));
        if (tx == 0) g_Smax[b * CC + c] = rowm;
    }
}

// ---------------- K3a: partial column softmax stats (over C, masked) -------
__global__ void k_colreduce(const int* __restrict__ qmask) {
    int b = blockIdx.x;
    int chunk = blockIdx.y;  // 4 chunks of 128 c each
    int q = threadIdx.x;     // 128 threads
    float mterm = (1.0f - (float)qmask[b * QQ + q]) * NEGV;
    float m = FLOOR_F, s = 0.f;
    const float* Sp = g_S + (b * CC + chunk * 128) * QQ + q;
#pragma unroll 4
    for (int c = 0; c < 128; c++) {
        float x = Sp[c * QQ] + mterm;  // absorption for masked q happens HERE
        float nm = fmaxf(m, x);
        s = s * __expf(m - nm) + __expf(x - nm);
        m = nm;
    }
    g_pmax[(chunk * BB + b) * QQ + q] = m;
    g_psum[(chunk * BB + b) * QQ + q] = s;
}

// ---------------- K3b: combine partial stats -------------------------------
__global__ void k_colcombine() {
    int i = blockIdx.x * blockDim.x + threadIdx.x;
    if (i >= BB * QQ) return;
    float m = g_pmax[i];
#pragma unroll
    for (int ch = 1; ch < 4; ch++) m = fmaxf(m, g_pmax[ch * BB * QQ + i]);
    float s = 0.f;
#pragma unroll
    for (int ch = 0; ch < 4; ch++)
        s += g_psum[ch * BB * QQ + i] * __expf(g_pmax[ch * BB * QQ + i] - m);
    g_colmax[i] = m;
    g_colinv[i] = 1.0f / s;
}

// ---------------- K_cdash: softmax(S_max + cmask) over c, then GEMV --------
// grid (B, D/128), block 128: each block recomputes the (cheap) softmax over
// 512 c values, then each thread reduces one d over all 512 c.
__global__ void __launch_bounds__(128) k_cdash(const float* __restrict__ cont,
                                               const int* __restrict__ cmask) {
    __shared__ float ps[CC];
    __shared__ float red[128];
    int b = blockIdx.x;
    int d0 = blockIdx.y * 128;
    int t = threadIdx.x;

    float xv[4];
    float lm = FLOOR_F;
#pragma unroll
    for (int r = 0; r < 4; r++) {
        int c = t + 128 * r;
        float x = g_Smax[b * CC + c] + (1.0f - (float)cmask[b * CC + c]) * NEGV;
        xv[r] = x;
        lm = fmaxf(lm, x);
    }
    red[t] = lm;
    __syncthreads();
    for (int o = 64; o; o >>= 1) {
        if (t < o) red[t] = fmaxf(red[t], red[t + o]);
        __syncthreads();
    }
    float m = red[0];
    __syncthreads();
    float lsum = 0.f;
#pragma unroll
    for (int r = 0; r < 4; r++) {
        float e = __expf(xv[r] - m);
        ps[t + 128 * r] = e;
        lsum += e;
    }
    red[t] = lsum;
    __syncthreads();
    for (int o = 64; o; o >>= 1) {
        if (t < o) red[t] += red[t + o];
        __syncthreads();
    }
    float inv = 1.0f / red[0];
    __syncthreads();

    int d = d0 + t;
    const float* cb = cont + b * CC * DD + d;
    float a0 = 0.f, a1 = 0.f, a2 = 0.f, a3 = 0.f;
    for (int c = 0; c < CC; c += 4) {
        a0 += ps[c + 0] * cb[(c + 0) * DD];
        a1 += ps[c + 1] * cb[(c + 1) * DD];
        a2 += ps[c + 2] * cb[(c + 2) * DD];
        a3 += ps[c + 3] * cb[(c + 3) * DD];
    }
    g_cdash[b * DD + d] = ((a0 + a1) + (a2 + a3)) * inv;
}

// ---------------- K4: c2q GEMM (P @ q) + full output epilogue --------------
// per batch: M=C (tiles 64), N=D (tiles 128), K=Q=128 (full, in 16-chunks)
// P built once in smem from S via exp; epilogue writes all 4 output segments.
__global__ void __launch_bounds__(256) k_out(const float* __restrict__ cont,
                                             const float* __restrict__ ques,
                                             const int* __restrict__ qmask,
                                             float* __restrict__ out) {
    __shared__ float Ps[64][QQ + 1];   // P[c][q], 33 KB
    __shared__ float Qs[16][132];      // q[k][d] chunk, 8.4 KB
    __shared__ float cm[QQ], ci[QQ], cmt[QQ], cd[128];

    int b = blockIdx.z;
    int c0 = blockIdx.y * 64;
    int d0 = blockIdx.x * 128;
    int t = threadIdx.x, tx = t & 15, ty = t >> 4;

    if (t < QQ) {
        cm[t] = g_colmax[b * QQ + t];
        ci[t] = g_colinv[b * QQ + t];
        cmt[t] = (1.0f - (float)qmask[b * QQ + t]) * NEGV;
    }
    if (t < 128) cd[t] = g_cdash[b * DD + d0 + t];
    __syncthreads();

    // build P tile 64x128
    const float* Sp = g_S + (b * CC + c0) * QQ;
#pragma unroll
    for (int r = 0; r < 32; r++) {
        int idx = t + 256 * r;
        int c = idx >> 7, q = idx & 127;
        float x = Sp[idx] + cmt[q];  // absorption first (matches reference fp32)
        Ps[c][q] = __expf(x - cm[q]) * ci[q];
    }
    __syncthreads();

    float acc[4][8];
#pragma unroll
    for (int i = 0; i < 4; i++)
#pragma unroll
        for (int j = 0; j < 8; j++) acc[i][j] = 0.f;

    for (int k0 = 0; k0 < QQ; k0 += 16) {
        // load q chunk 16 x 128 = 512 float4, two per thread
#pragma unroll
        for (int r = 0; r < 2; r++) {
            int f = t + 256 * r;
            int qq = f >> 5, d4 = f & 31;
            float4 x = *reinterpret_cast<const float4*>(
                ques + (b * QQ + k0 + qq) * DD + d0 + d4 * 4);
            *reinterpret_cast<float4*>(&Qs[qq][d4 * 4]) = x;
        }
        __syncthreads();
#pragma unroll
        for (int k = 0; k < 16; k++) {
            float pv[4], qv[8];
#pragma unroll
            for (int i = 0; i < 4; i++) pv[i] = Ps[ty * 4 + i][k0 + k];
#pragma unroll
            for (int j = 0; j < 8; j++) qv[j] = Qs[k][tx + 16 * j];
#pragma unroll
            for (int i = 0; i < 4; i++)
#pragma unroll
                for (int j = 0; j < 8; j++) acc[i][j] += pv[i] * qv[j];
        }
        __syncthreads();
    }

    // epilogue: out = [c | c2q | c*c2q | c*c_dash]
#pragma unroll
    for (int i = 0; i < 4; i++) {
        int c = c0 + ty * 4 + i;
        const float* crow = cont + (b * CC + c) * DD + d0;
        float* orow = out + (b * CC + c) * (4 * DD) + d0;
#pragma unroll
        for (int j = 0; j < 8; j++) {
            int dd = tx + 16 * j;
            float cv = crow[dd];
            float c2q = acc[i][j];
            orow[dd] = cv;
            orow[DD + dd] = c2q;
            orow[2 * DD + dd] = cv * c2q;
            orow[3 * DD + dd] = cv * cd[dd];
        }
    }
}

// ---------------- launch ---------------------------------------------------
extern "C" void kernel_launch(void* const* d_in, const int* in_sizes, int n_in,
                              void* d_out, int out_size) {
    const float* cont = (const float*)d_in[0];       // (32,512,768) f32
    const int* cmask = (const int*)d_in[1];          // (32,512) i32
    const float* ques = (const float*)d_in[2];       // (32,128,768) f32
    const int* qmask = (const int*)d_in[3];          // (32,128) i32
    const float* SW = (const float*)d_in[4];         // (2304,) f32
    float* out = (float*)d_out;                      // (32,512,3072) f32

    k_rowdots<<<(BB * CC + BB * QQ) / 8, 256>>>(cont, ques, SW);
    k_sim<<<dim3(CC / 64, 1, BB), 256>>>(cont, ques, SW);
    k_colreduce<<<dim3(BB, 4), 128>>>(qmask);
    k_colcombine<<<(BB * QQ + 255) / 256, 256>>>();
    k_cdash<<<dim3(BB, DD / 128), 128>>>(cont, cmask);
    k_out<<<dim3(DD / 128, CC / 64, BB), 256>>>(cont, ques, qmask, out);
}

// round 4
// speedup vs baseline: 2.3973x; 2.3973x over previous
#include <cuda_runtime.h>
#include <cstdint>

#define BB 32
#define CC 512
#define QQ 128
#define DD 768
#define NEGV (-1e30f)
#define FLOOR_F (-3.402823466e38f)

// ---------------- scratch (device globals) ---------------------------------
__device__ float g_S[BB * CC * QQ];        // similarity, 8 MB
__device__ float g_qT[BB * DD * QQ];       // q transposed [b][d][q], 12 MB
__device__ float g_a[BB * CC];             // dot(c, w1)
__device__ float g_bq[BB * QQ];            // dot(q, w2)
__device__ float g_Smax[BB * CC];          // max over q of S
__device__ float g_pmax[4 * BB * QQ];
__device__ float g_psum[4 * BB * QQ];
__device__ float g_colmax[BB * QQ];
__device__ float g_colinv[BB * QQ];
__device__ float g_cdash[BB * DD];

// ---------------- mma.sync tf32 helpers ------------------------------------
__device__ __forceinline__ uint32_t f2tf(float f) {
    uint32_t r;
    asm("cvt.rna.tf32.f32 %0, %1;" : "=r"(r) : "f"(f));
    return r;
}

__device__ __forceinline__ void mma_tf32(float* c, const uint32_t* a,
                                         const uint32_t* b) {
    asm volatile(
        "mma.sync.aligned.m16n8k8.row.col.f32.tf32.tf32.f32 "
        "{%0,%1,%2,%3}, {%4,%5,%6,%7}, {%8,%9}, {%0,%1,%2,%3};"
        : "+f"(c[0]), "+f"(c[1]), "+f"(c[2]), "+f"(c[3])
        : "r"(a[0]), "r"(a[1]), "r"(a[2]), "r"(a[3]), "r"(b[0]), "r"(b[1]));
}

// ---------------- K1: row dots ---------------------------------------------
__global__ void k_rowdots(const float* __restrict__ cont,
                          const float* __restrict__ ques,
                          const float* __restrict__ SW) {
    int warp = (blockIdx.x * blockDim.x + threadIdx.x) >> 5;
    int lane = threadIdx.x & 31;
    const float* src;
    const float* w;
    float* dst;
    if (warp < BB * CC) {
        src = cont + (size_t)warp * DD; w = SW; dst = g_a + warp;
    } else {
        int r = warp - BB * CC;
        if (r >= BB * QQ) return;
        src = ques + (size_t)r * DD; w = SW + DD; dst = g_bq + r;
    }
    float acc = 0.f;
#pragma unroll
    for (int i = 0; i < 6; i++) {
        int k4 = lane + 32 * i;
        float4 x = reinterpret_cast<const float4*>(src)[k4];
        float4 ww = reinterpret_cast<const float4*>(w)[k4];
        acc += x.x * ww.x + x.y * ww.y + x.z * ww.z + x.w * ww.w;
    }
#pragma unroll
    for (int o = 16; o; o >>= 1) acc += __shfl_xor_sync(0xffffffffu, acc, o);
    if (lane == 0) *dst = acc;
}

// ---------------- K1b: transpose q -> qT[b][d][q] --------------------------
__global__ void k_qtrans(const float* __restrict__ ques) {
    __shared__ float tile[32][33];
    int b = blockIdx.z;
    int q0 = blockIdx.x * 32;
    int d0 = blockIdx.y * 32;
    int lx = threadIdx.x, ly = threadIdx.y;
#pragma unroll
    for (int i = 0; i < 32; i += 8)
        tile[ly + i][lx] = ques[((size_t)b * QQ + q0 + ly + i) * DD + d0 + lx];
    __syncthreads();
#pragma unroll
    for (int i = 0; i < 32; i += 8)
        g_qT[((size_t)b * DD + d0 + ly + i) * QQ + q0 + lx] = tile[lx][ly + i];
}

// ---------------- K2: similarity via mma.sync tf32 -------------------------
// grid (C/128, B), block 256 (8 warps, 4x2). Tile M=128(c), N=128(q), KT=16.
// S[c][q] = a[c] + bq[q] + sum_d c[c,d] * (w3[d]*q[q,d]); fused row max.
__global__ void __launch_bounds__(256) k_sim_mma(const float* __restrict__ cont,
                                                 const float* __restrict__ ques,
                                                 const float* __restrict__ SW) {
    __shared__ uint32_t As[128][20];
    __shared__ uint32_t Bs[128][20];
    __shared__ float redm[128][2];
    __shared__ float bq_s[128];

    int t = threadIdx.x;
    int wid = t >> 5, lane = t & 31;
    int gp = lane >> 2, tq = lane & 3;
    int warp_m = wid & 3, warp_n = wid >> 2;
    int mbase = warp_m * 32, nbase = warp_n * 64;
    int b = blockIdx.y;
    int c0 = blockIdx.x * 128;

    if (t < QQ) bq_s[t] = g_bq[b * QQ + t];

    const float* cbase = cont + ((size_t)b * CC + c0) * DD;
    const float* qbase = ques + (size_t)b * QQ * DD;
    const float* w3 = SW + 2 * DD;

    int lrowA = t >> 2, lquad = t & 3;

    float acc[2][8][4];
#pragma unroll
    for (int mt = 0; mt < 2; mt++)
#pragma unroll
        for (int nt = 0; nt < 8; nt++)
#pragma unroll
            for (int j = 0; j < 4; j++) acc[mt][nt][j] = 0.f;

    float4 ar[2], br[2], w3r;
    {
        int k0 = 0;
        w3r = *(const float4*)(w3 + k0 + lquad * 4);
#pragma unroll
        for (int r = 0; r < 2; r++) {
            int row = lrowA + 64 * r;
            ar[r] = *(const float4*)(cbase + (size_t)row * DD + k0 + lquad * 4);
            br[r] = *(const float4*)(qbase + (size_t)row * DD + k0 + lquad * 4);
        }
    }

    for (int i = 0; i < 48; i++) {
        if (i) __syncthreads();
        // STS with cvt (+ w3 scale on B)
#pragma unroll
        for (int r = 0; r < 2; r++) {
            int row = lrowA + 64 * r;
            As[row][lquad * 4 + 0] = f2tf(ar[r].x);
            As[row][lquad * 4 + 1] = f2tf(ar[r].y);
            As[row][lquad * 4 + 2] = f2tf(ar[r].z);
            As[row][lquad * 4 + 3] = f2tf(ar[r].w);
            Bs[row][lquad * 4 + 0] = f2tf(br[r].x * w3r.x);
            Bs[row][lquad * 4 + 1] = f2tf(br[r].y * w3r.y);
            Bs[row][lquad * 4 + 2] = f2tf(br[r].z * w3r.z);
            Bs[row][lquad * 4 + 3] = f2tf(br[r].w * w3r.w);
        }
        __syncthreads();
        if (i < 47) {
            int k0 = 16 * (i + 1);
            w3r = *(const float4*)(w3 + k0 + lquad * 4);
#pragma unroll
            for (int r = 0; r < 2; r++) {
                int row = lrowA + 64 * r;
                ar[r] = *(const float4*)(cbase + (size_t)row * DD + k0 + lquad * 4);
                br[r] = *(const float4*)(qbase + (size_t)row * DD + k0 + lquad * 4);
            }
        }
#pragma unroll
        for (int ks = 0; ks < 2; ks++) {
            int kk = ks * 8;
            uint32_t aF[2][4];
#pragma unroll
            for (int mt = 0; mt < 2; mt++) {
                int mrow = mbase + mt * 16 + gp;
                aF[mt][0] = As[mrow][kk + tq];
                aF[mt][1] = As[mrow + 8][kk + tq];
                aF[mt][2] = As[mrow][kk + tq + 4];
                aF[mt][3] = As[mrow + 8][kk + tq + 4];
            }
            uint32_t bF[8][2];
#pragma unroll
            for (int nt = 0; nt < 8; nt++) {
                int nrow = nbase + nt * 8 + gp;
                bF[nt][0] = Bs[nrow][kk + tq];
                bF[nt][1] = Bs[nrow][kk + tq + 4];
            }
#pragma unroll
            for (int mt = 0; mt < 2; mt++)
#pragma unroll
                for (int nt = 0; nt < 8; nt++)
                    mma_tf32(acc[mt][nt], aF[mt], bF[nt]);
        }
    }
    __syncthreads();

    // epilogue: add a + bq, write S, fused row max
#pragma unroll
    for (int mt = 0; mt < 2; mt++) {
        int rl0 = mbase + mt * 16 + gp;
        int rl1 = rl0 + 8;
        float a0v = g_a[b * CC + c0 + rl0];
        float a1v = g_a[b * CC + c0 + rl1];
        float m0 = FLOOR_F, m1 = FLOOR_F;
        float* S0 = g_S + ((size_t)b * CC + c0 + rl0) * QQ;
        float* S1 = g_S + ((size_t)b * CC + c0 + rl1) * QQ;
#pragma unroll
        for (int nt = 0; nt < 8; nt++) {
            int q = nbase + nt * 8 + 2 * tq;
            float bq0 = bq_s[q], bq1 = bq_s[q + 1];
            float s00 = acc[mt][nt][0] + a0v + bq0;
            float s01 = acc[mt][nt][1] + a0v + bq1;
            float s10 = acc[mt][nt][2] + a1v + bq0;
            float s11 = acc[mt][nt][3] + a1v + bq1;
            *(float2*)(S0 + q) = make_float2(s00, s01);
            *(float2*)(S1 + q) = make_float2(s10, s11);
            m0 = fmaxf(m0, fmaxf(s00, s01));
            m1 = fmaxf(m1, fmaxf(s10, s11));
        }
        m0 = fmaxf(m0, __shfl_xor_sync(0xffffffffu, m0, 1));
        m0 = fmaxf(m0, __shfl_xor_sync(0xffffffffu, m0, 2));
        m1 = fmaxf(m1, __shfl_xor_sync(0xffffffffu, m1, 1));
        m1 = fmaxf(m1, __shfl_xor_sync(0xffffffffu, m1, 2));
        if (tq == 0) {
            redm[rl0][warp_n] = m0;
            redm[rl1][warp_n] = m1;
        }
    }
    __syncthreads();
    if (t < 128)
        g_Smax[b * CC + c0 + t] = fmaxf(redm[t][0], redm[t][1]);
}

// ---------------- K3a/K3b: column softmax stats ----------------------------
__global__ void k_colreduce(const int* __restrict__ qmask) {
    int b = blockIdx.x;
    int chunk = blockIdx.y;
    int q = threadIdx.x;
    float mterm = (1.0f - (float)qmask[b * QQ + q]) * NEGV;
    float m = FLOOR_F, s = 0.f;
    const float* Sp = g_S + ((size_t)b * CC + chunk * 128) * QQ + q;
#pragma unroll 4
    for (int c = 0; c < 128; c++) {
        float x = Sp[(size_t)c * QQ] + mterm;
        float nm = fmaxf(m, x);
        s = s * __expf(m - nm) + __expf(x - nm);
        m = nm;
    }
    g_pmax[(chunk * BB + b) * QQ + q] = m;
    g_psum[(chunk * BB + b) * QQ + q] = s;
}

__global__ void k_colcombine() {
    int i = blockIdx.x * blockDim.x + threadIdx.x;
    if (i >= BB * QQ) return;
    float m = g_pmax[i];
#pragma unroll
    for (int ch = 1; ch < 4; ch++) m = fmaxf(m, g_pmax[ch * BB * QQ + i]);
    float s = 0.f;
#pragma unroll
    for (int ch = 0; ch < 4; ch++)
        s += g_psum[ch * BB * QQ + i] * __expf(g_pmax[ch * BB * QQ + i] - m);
    g_colmax[i] = m;
    g_colinv[i] = 1.0f / s;
}

// ---------------- K_cdash --------------------------------------------------
__global__ void __launch_bounds__(128) k_cdash(const float* __restrict__ cont,
                                               const int* __restrict__ cmask) {
    __shared__ float ps[CC];
    __shared__ float red[128];
    int b = blockIdx.x;
    int d0 = blockIdx.y * 128;
    int t = threadIdx.x;

    float xv[4];
    float lm = FLOOR_F;
#pragma unroll
    for (int r = 0; r < 4; r++) {
        int c = t + 128 * r;
        float x = g_Smax[b * CC + c] + (1.0f - (float)cmask[b * CC + c]) * NEGV;
        xv[r] = x;
        lm = fmaxf(lm, x);
    }
    red[t] = lm;
    __syncthreads();
    for (int o = 64; o; o >>= 1) {
        if (t < o) red[t] = fmaxf(red[t], red[t + o]);
        __syncthreads();
    }
    float m = red[0];
    __syncthreads();
    float lsum = 0.f;
#pragma unroll
    for (int r = 0; r < 4; r++) {
        float e = __expf(xv[r] - m);
        ps[t + 128 * r] = e;
        lsum += e;
    }
    red[t] = lsum;
    __syncthreads();
    for (int o = 64; o; o >>= 1) {
        if (t < o) red[t] += red[t + o];
        __syncthreads();
    }
    float inv = 1.0f / red[0];
    __syncthreads();

    int d = d0 + t;
    const float* cb = cont + (size_t)b * CC * DD + d;
    float a0 = 0.f, a1 = 0.f, a2 = 0.f, a3 = 0.f;
    for (int c = 0; c < CC; c += 4) {
        a0 += ps[c + 0] * cb[(size_t)(c + 0) * DD];
        a1 += ps[c + 1] * cb[(size_t)(c + 1) * DD];
        a2 += ps[c + 2] * cb[(size_t)(c + 2) * DD];
        a3 += ps[c + 3] * cb[(size_t)(c + 3) * DD];
    }
    g_cdash[b * DD + d] = ((a0 + a1) + (a2 + a3)) * inv;
}

// ---------------- K4: c2q = P @ qT via mma.sync + output epilogue ----------
// grid (D/128, C/128, B), block 256. Tile M=128(c), N=128(d), K=Q=128.
__global__ void __launch_bounds__(256) k_out_mma(const float* __restrict__ cont,
                                                 const int* __restrict__ qmask,
                                                 float* __restrict__ out) {
    __shared__ uint32_t Ps[128][20];
    __shared__ uint32_t Qs[128][20];
    __shared__ float cm_s[128], ci_s[128], cmt_s[128], cd_s[128];

    int t = threadIdx.x;
    int wid = t >> 5, lane = t & 31;
    int gp = lane >> 2, tq = lane & 3;
    int warp_m = wid & 3, warp_n = wid >> 2;
    int mbase = warp_m * 32, nbase = warp_n * 64;
    int b = blockIdx.z;
    int c0 = blockIdx.y * 128;
    int d0 = blockIdx.x * 128;

    if (t < QQ) {
        cm_s[t] = g_colmax[b * QQ + t];
        ci_s[t] = g_colinv[b * QQ + t];
        cmt_s[t] = (1.0f - (float)qmask[b * QQ + t]) * NEGV;
    }
    if (t < 128) cd_s[t] = g_cdash[b * DD + d0 + t];
    __syncthreads();

    const float* Sbase = g_S + ((size_t)b * CC + c0) * QQ;
    const float* qTbase = g_qT + ((size_t)b * DD + d0) * QQ;

    int lrowA = t >> 2, lquad = t & 3;

    float acc[2][8][4];
#pragma unroll
    for (int mt = 0; mt < 2; mt++)
#pragma unroll
        for (int nt = 0; nt < 8; nt++)
#pragma unroll
            for (int j = 0; j < 4; j++) acc[mt][nt][j] = 0.f;

    float4 sr[2], qr[2];
    {
        int k0 = 0;
#pragma unroll
        for (int r = 0; r < 2; r++) {
            int row = lrowA + 64 * r;
            sr[r] = *(const float4*)(Sbase + (size_t)row * QQ + k0 + lquad * 4);
            qr[r] = *(const float4*)(qTbase + (size_t)row * QQ + k0 + lquad * 4);
        }
    }

    for (int i = 0; i < 8; i++) {
        int k0 = 16 * i;
        if (i) __syncthreads();
        float4 cmt4 = *(const float4*)(cmt_s + k0 + lquad * 4);
        float4 cm4 = *(const float4*)(cm_s + k0 + lquad * 4);
        float4 ci4 = *(const float4*)(ci_s + k0 + lquad * 4);
#pragma unroll
        for (int r = 0; r < 2; r++) {
            int row = lrowA + 64 * r;
            // absorption order: (s + cmt) - cm, matches reference fp32
            Ps[row][lquad * 4 + 0] = f2tf(__expf((sr[r].x + cmt4.x) - cm4.x) * ci4.x);
            Ps[row][lquad * 4 + 1] = f2tf(__expf((sr[r].y + cmt4.y) - cm4.y) * ci4.y);
            Ps[row][lquad * 4 + 2] = f2tf(__expf((sr[r].z + cmt4.z) - cm4.z) * ci4.z);
            Ps[row][lquad * 4 + 3] = f2tf(__expf((sr[r].w + cmt4.w) - cm4.w) * ci4.w);
            Qs[row][lquad * 4 + 0] = f2tf(qr[r].x);
            Qs[row][lquad * 4 + 1] = f2tf(qr[r].y);
            Qs[row][lquad * 4 + 2] = f2tf(qr[r].z);
            Qs[row][lquad * 4 + 3] = f2tf(qr[r].w);
        }
        __syncthreads();
        if (i < 7) {
            int k1 = 16 * (i + 1);
#pragma unroll
            for (int r = 0; r < 2; r++) {
                int row = lrowA + 64 * r;
                sr[r] = *(const float4*)(Sbase + (size_t)row * QQ + k1 + lquad * 4);
                qr[r] = *(const float4*)(qTbase + (size_t)row * QQ + k1 + lquad * 4);
            }
        }
#pragma unroll
        for (int ks = 0; ks < 2; ks++) {
            int kk = ks * 8;
            uint32_t aF[2][4];
#pragma unroll
            for (int mt = 0; mt < 2; mt++) {
                int mrow = mbase + mt * 16 + gp;
                aF[mt][0] = Ps[mrow][kk + tq];
                aF[mt][1] = Ps[mrow + 8][kk + tq];
                aF[mt][2] = Ps[mrow][kk + tq + 4];
                aF[mt][3] = Ps[mrow + 8][kk + tq + 4];
            }
            uint32_t bF[8][2];
#pragma unroll
            for (int nt = 0; nt < 8; nt++) {
                int nrow = nbase + nt * 8 + gp;
                bF[nt][0] = Qs[nrow][kk + tq];
                bF[nt][1] = Qs[nrow][kk + tq + 4];
            }
#pragma unroll
            for (int mt = 0; mt < 2; mt++)
#pragma unroll
                for (int nt = 0; nt < 8; nt++)
                    mma_tf32(acc[mt][nt], aF[mt], bF[nt]);
        }
    }

    // epilogue: out = [c | c2q | c*c2q | c*c_dash], straight from fragments
#pragma unroll
    for (int mt = 0; mt < 2; mt++) {
#pragma unroll
        for (int half = 0; half < 2; half++) {
            int rl = mbase + mt * 16 + gp + half * 8;
            size_t crow = (size_t)b * CC + c0 + rl;
            const float* crp = cont + crow * DD;
            float* orp = out + crow * (4 * DD);
#pragma unroll
            for (int nt = 0; nt < 8; nt++) {
                int dloc = nbase + nt * 8 + 2 * tq;
                int dcol = d0 + dloc;
                float c2q0 = acc[mt][nt][half * 2 + 0];
                float c2q1 = acc[mt][nt][half * 2 + 1];
                float2 cv = *(const float2*)(crp + dcol);
                float cd0 = cd_s[dloc], cd1 = cd_s[dloc + 1];
                *(float2*)(orp + dcol) = cv;
                *(float2*)(orp + DD + dcol) = make_float2(c2q0, c2q1);
                *(float2*)(orp + 2 * DD + dcol) = make_float2(cv.x * c2q0, cv.y * c2q1);
                *(float2*)(orp + 3 * DD + dcol) = make_float2(cv.x * cd0, cv.y * cd1);
            }
        }
    }
}

// ---------------- launch ---------------------------------------------------
extern "C" void kernel_launch(void* const* d_in, const int* in_sizes, int n_in,
                              void* d_out, int out_size) {
    const float* cont = (const float*)d_in[0];   // (32,512,768) f32
    const int* cmask = (const int*)d_in[1];      // (32,512) i32
    const float* ques = (const float*)d_in[2];   // (32,128,768) f32
    const int* qmask = (const int*)d_in[3];      // (32,128) i32
    const float* SW = (const float*)d_in[4];     // (2304,) f32
    float* out = (float*)d_out;                  // (32,512,3072) f32

    k_rowdots<<<2560, 256>>>(cont, ques, SW);
    k_qtrans<<<dim3(QQ / 32, DD / 32, BB), dim3(32, 8)>>>(ques);
    k_sim_mma<<<dim3(CC / 128, BB), 256>>>(cont, ques, SW);
    k_colreduce<<<dim3(BB, 4), 128>>>(qmask);
    k_colcombine<<<(BB * QQ + 255) / 256, 256>>>();
    k_cdash<<<dim3(BB, DD / 128), 128>>>(cont, cmask);
    k_out_mma<<<dim3(DD / 128, CC / 128, BB), 256>>>(cont, qmask, out);
}

// round 5
// speedup vs baseline: 2.8824x; 1.2023x over previous
#include <cuda_runtime.h>
#include <cstdint>

#define BB 32
#define CC 512
#define QQ 128
#define DD 768
#define NEGV (-1e30f)
#define FLOOR_F (-3.402823466e38f)

// ---------------- scratch (device globals) ---------------------------------
__device__ float g_S[BB * CC * QQ];        // similarity, 8 MB
__device__ float g_qT[BB * DD * QQ];       // q transposed [b][d][q], 12 MB
__device__ float g_a[BB * CC];             // dot(c, w1)
__device__ float g_bq[BB * QQ];            // dot(q, w2)
__device__ float g_Smax[BB * CC];          // max over q of S
__device__ float g_pmax[4 * BB * QQ];      // per-chunk column max
__device__ float g_psum[4 * BB * QQ];      // per-chunk column sum
__device__ float g_colmax[BB * QQ];
__device__ float g_colinv[BB * QQ];
__device__ float g_cdpart[4 * BB * DD];    // c_dash partials per c-chunk
__device__ float g_cdash[BB * DD];

// ---------------- mma.sync tf32 helpers ------------------------------------
__device__ __forceinline__ uint32_t f2tf(float f) {
    uint32_t r;
    asm("cvt.rna.tf32.f32 %0, %1;" : "=r"(r) : "f"(f));
    return r;
}

__device__ __forceinline__ void mma_tf32(float* c, const uint32_t* a,
                                         const uint32_t* b) {
    asm volatile(
        "mma.sync.aligned.m16n8k8.row.col.f32.tf32.tf32.f32 "
        "{%0,%1,%2,%3}, {%4,%5,%6,%7}, {%8,%9}, {%0,%1,%2,%3};"
        : "+f"(c[0]), "+f"(c[1]), "+f"(c[2]), "+f"(c[3])
        : "r"(a[0]), "r"(a[1]), "r"(a[2]), "r"(a[3]), "r"(b[0]), "r"(b[1]));
}

// ---------------- K1: row dots ---------------------------------------------
__global__ void k_rowdots(const float* __restrict__ cont,
                          const float* __restrict__ ques,
                          const float* __restrict__ SW) {
    int warp = (blockIdx.x * blockDim.x + threadIdx.x) >> 5;
    int lane = threadIdx.x & 31;
    const float* src;
    const float* w;
    float* dst;
    if (warp < BB * CC) {
        src = cont + (size_t)warp * DD; w = SW; dst = g_a + warp;
    } else {
        int r = warp - BB * CC;
        if (r >= BB * QQ) return;
        src = ques + (size_t)r * DD; w = SW + DD; dst = g_bq + r;
    }
    float acc = 0.f;
#pragma unroll
    for (int i = 0; i < 6; i++) {
        int k4 = lane + 32 * i;
        float4 x = reinterpret_cast<const float4*>(src)[k4];
        float4 ww = reinterpret_cast<const float4*>(w)[k4];
        acc += x.x * ww.x + x.y * ww.y + x.z * ww.z + x.w * ww.w;
    }
#pragma unroll
    for (int o = 16; o; o >>= 1) acc += __shfl_xor_sync(0xffffffffu, acc, o);
    if (lane == 0) *dst = acc;
}

// ---------------- K1b: transpose q -> qT[b][d][q] --------------------------
__global__ void k_qtrans(const float* __restrict__ ques) {
    __shared__ float tile[32][33];
    int b = blockIdx.z;
    int q0 = blockIdx.x * 32;
    int d0 = blockIdx.y * 32;
    int lx = threadIdx.x, ly = threadIdx.y;
#pragma unroll
    for (int i = 0; i < 32; i += 8)
        tile[ly + i][lx] = ques[((size_t)b * QQ + q0 + ly + i) * DD + d0 + lx];
    __syncthreads();
#pragma unroll
    for (int i = 0; i < 32; i += 8)
        g_qT[((size_t)b * DD + d0 + ly + i) * QQ + q0 + lx] = tile[lx][ly + i];
}

// ---------------- K2: similarity via mma.sync tf32 + fused col stats -------
// grid (C/128, B), block 256 (8 warps, 4x2). Tile M=128(c), N=128(q), KT=16.
__global__ void __launch_bounds__(256) k_sim_mma(const float* __restrict__ cont,
                                                 const float* __restrict__ ques,
                                                 const float* __restrict__ SW,
                                                 const int* __restrict__ qmask) {
    __shared__ uint32_t As[128][20];
    __shared__ uint32_t Bs[128][20];
    __shared__ float redm[128][2];
    __shared__ float bq_s[128];
    __shared__ float cmt_s[128];
    __shared__ float colm[128][4];
    __shared__ float colsum[128][4];
    __shared__ float mC_s[128];

    int t = threadIdx.x;
    int wid = t >> 5, lane = t & 31;
    int gp = lane >> 2, tq = lane & 3;
    int warp_m = wid & 3, warp_n = wid >> 2;
    int mbase = warp_m * 32, nbase = warp_n * 64;
    int b = blockIdx.y;
    int c0 = blockIdx.x * 128;

    if (t < QQ) {
        bq_s[t] = g_bq[b * QQ + t];
        cmt_s[t] = (1.0f - (float)qmask[b * QQ + t]) * NEGV;
    }

    const float* cbase = cont + ((size_t)b * CC + c0) * DD;
    const float* qbase = ques + (size_t)b * QQ * DD;
    const float* w3 = SW + 2 * DD;

    int lrowA = t >> 2, lquad = t & 3;

    float acc[2][8][4];
#pragma unroll
    for (int mt = 0; mt < 2; mt++)
#pragma unroll
        for (int nt = 0; nt < 8; nt++)
#pragma unroll
            for (int j = 0; j < 4; j++) acc[mt][nt][j] = 0.f;

    float4 ar[2], br[2], w3r;
    {
        w3r = *(const float4*)(w3 + lquad * 4);
#pragma unroll
        for (int r = 0; r < 2; r++) {
            int row = lrowA + 64 * r;
            ar[r] = *(const float4*)(cbase + (size_t)row * DD + lquad * 4);
            br[r] = *(const float4*)(qbase + (size_t)row * DD + lquad * 4);
        }
    }

    for (int i = 0; i < 48; i++) {
        if (i) __syncthreads();
#pragma unroll
        for (int r = 0; r < 2; r++) {
            int row = lrowA + 64 * r;
            As[row][lquad * 4 + 0] = f2tf(ar[r].x);
            As[row][lquad * 4 + 1] = f2tf(ar[r].y);
            As[row][lquad * 4 + 2] = f2tf(ar[r].z);
            As[row][lquad * 4 + 3] = f2tf(ar[r].w);
            Bs[row][lquad * 4 + 0] = f2tf(br[r].x * w3r.x);
            Bs[row][lquad * 4 + 1] = f2tf(br[r].y * w3r.y);
            Bs[row][lquad * 4 + 2] = f2tf(br[r].z * w3r.z);
            Bs[row][lquad * 4 + 3] = f2tf(br[r].w * w3r.w);
        }
        __syncthreads();
        if (i < 47) {
            int k0 = 16 * (i + 1);
            w3r = *(const float4*)(w3 + k0 + lquad * 4);
#pragma unroll
            for (int r = 0; r < 2; r++) {
                int row = lrowA + 64 * r;
                ar[r] = *(const float4*)(cbase + (size_t)row * DD + k0 + lquad * 4);
                br[r] = *(const float4*)(qbase + (size_t)row * DD + k0 + lquad * 4);
            }
        }
#pragma unroll
        for (int ks = 0; ks < 2; ks++) {
            int kk = ks * 8;
            uint32_t aF[2][4];
#pragma unroll
            for (int mt = 0; mt < 2; mt++) {
                int mrow = mbase + mt * 16 + gp;
                aF[mt][0] = As[mrow][kk + tq];
                aF[mt][1] = As[mrow + 8][kk + tq];
                aF[mt][2] = As[mrow][kk + tq + 4];
                aF[mt][3] = As[mrow + 8][kk + tq + 4];
            }
            uint32_t bF[8][2];
#pragma unroll
            for (int nt = 0; nt < 8; nt++) {
                int nrow = nbase + nt * 8 + gp;
                bF[nt][0] = Bs[nrow][kk + tq];
                bF[nt][1] = Bs[nrow][kk + tq + 4];
            }
#pragma unroll
            for (int mt = 0; mt < 2; mt++)
#pragma unroll
                for (int nt = 0; nt < 8; nt++)
                    mma_tf32(acc[mt][nt], aF[mt], bF[nt]);
        }
    }
    __syncthreads();

    // epilogue: s = acc + a + bq (kept in acc), write S, fused row max
#pragma unroll
    for (int mt = 0; mt < 2; mt++) {
        int rl0 = mbase + mt * 16 + gp;
        int rl1 = rl0 + 8;
        float a0v = g_a[b * CC + c0 + rl0];
        float a1v = g_a[b * CC + c0 + rl1];
        float m0 = FLOOR_F, m1 = FLOOR_F;
        float* S0 = g_S + ((size_t)b * CC + c0 + rl0) * QQ;
        float* S1 = g_S + ((size_t)b * CC + c0 + rl1) * QQ;
#pragma unroll
        for (int nt = 0; nt < 8; nt++) {
            int q = nbase + nt * 8 + 2 * tq;
            float bq0 = bq_s[q], bq1 = bq_s[q + 1];
            float s00 = acc[mt][nt][0] + a0v + bq0;
            float s01 = acc[mt][nt][1] + a0v + bq1;
            float s10 = acc[mt][nt][2] + a1v + bq0;
            float s11 = acc[mt][nt][3] + a1v + bq1;
            acc[mt][nt][0] = s00; acc[mt][nt][1] = s01;
            acc[mt][nt][2] = s10; acc[mt][nt][3] = s11;
            *(float2*)(S0 + q) = make_float2(s00, s01);
            *(float2*)(S1 + q) = make_float2(s10, s11);
            m0 = fmaxf(m0, fmaxf(s00, s01));
            m1 = fmaxf(m1, fmaxf(s10, s11));
        }
        m0 = fmaxf(m0, __shfl_xor_sync(0xffffffffu, m0, 1));
        m0 = fmaxf(m0, __shfl_xor_sync(0xffffffffu, m0, 2));
        m1 = fmaxf(m1, __shfl_xor_sync(0xffffffffu, m1, 1));
        m1 = fmaxf(m1, __shfl_xor_sync(0xffffffffu, m1, 2));
        if (tq == 0) {
            redm[rl0][warp_n] = m0;
            redm[rl1][warp_n] = m1;
        }
    }
    __syncthreads();
    if (t < 128)
        g_Smax[b * CC + c0 + t] = fmaxf(redm[t][0], redm[t][1]);

    // fused column softmax stats over this 128-c chunk (x = s + cmt)
    float xm[8][2];
#pragma unroll
    for (int nt = 0; nt < 8; nt++)
#pragma unroll
        for (int c2 = 0; c2 < 2; c2++) {
            int q = nbase + nt * 8 + 2 * tq + c2;
            float m = fmaxf(fmaxf(acc[0][nt][c2], acc[0][nt][2 + c2]),
                            fmaxf(acc[1][nt][c2], acc[1][nt][2 + c2]));
            xm[nt][c2] = m + cmt_s[q];
        }
#pragma unroll
    for (int o = 4; o <= 16; o <<= 1)
#pragma unroll
        for (int nt = 0; nt < 8; nt++)
#pragma unroll
            for (int c2 = 0; c2 < 2; c2++)
                xm[nt][c2] = fmaxf(xm[nt][c2],
                                   __shfl_xor_sync(0xffffffffu, xm[nt][c2], o));
    if (gp == 0) {
#pragma unroll
        for (int nt = 0; nt < 8; nt++)
#pragma unroll
            for (int c2 = 0; c2 < 2; c2++)
                colm[nbase + nt * 8 + 2 * tq + c2][warp_m] = xm[nt][c2];
    }
    __syncthreads();
    if (t < 128)
        mC_s[t] = fmaxf(fmaxf(colm[t][0], colm[t][1]),
                        fmaxf(colm[t][2], colm[t][3]));
    __syncthreads();

    float xs[8][2];
#pragma unroll
    for (int nt = 0; nt < 8; nt++)
#pragma unroll
        for (int c2 = 0; c2 < 2; c2++) {
            int q = nbase + nt * 8 + 2 * tq + c2;
            float mC = mC_s[q], cmt = cmt_s[q];
            xs[nt][c2] = __expf((acc[0][nt][c2] + cmt) - mC)
                       + __expf((acc[0][nt][2 + c2] + cmt) - mC)
                       + __expf((acc[1][nt][c2] + cmt) - mC)
                       + __expf((acc[1][nt][2 + c2] + cmt) - mC);
        }
#pragma unroll
    for (int o = 4; o <= 16; o <<= 1)
#pragma unroll
        for (int nt = 0; nt < 8; nt++)
#pragma unroll
            for (int c2 = 0; c2 < 2; c2++)
                xs[nt][c2] += __shfl_xor_sync(0xffffffffu, xs[nt][c2], o);
    if (gp == 0) {
#pragma unroll
        for (int nt = 0; nt < 8; nt++)
#pragma unroll
            for (int c2 = 0; c2 < 2; c2++)
                colsum[nbase + nt * 8 + 2 * tq + c2][warp_m] = xs[nt][c2];
    }
    __syncthreads();
    if (t < 128) {
        int idx = (blockIdx.x * BB + b) * QQ + t;
        g_pmax[idx] = mC_s[t];
        g_psum[idx] = (colsum[t][0] + colsum[t][1]) + (colsum[t][2] + colsum[t][3]);
    }
}

// ---------------- K3: combine per-chunk column stats -----------------------
__global__ void k_colcombine() {
    int i = blockIdx.x * blockDim.x + threadIdx.x;
    if (i >= BB * QQ) return;
    float m = g_pmax[i];
#pragma unroll
    for (int ch = 1; ch < 4; ch++) m = fmaxf(m, g_pmax[ch * BB * QQ + i]);
    float s = 0.f;
#pragma unroll
    for (int ch = 0; ch < 4; ch++)
        s += g_psum[ch * BB * QQ + i] * __expf(g_pmax[ch * BB * QQ + i] - m);
    g_colmax[i] = m;
    g_colinv[i] = 1.0f / s;
}

// ---------------- K_cdash: partials over c-chunks --------------------------
// grid (B, D/128, 4), block 128
__global__ void __launch_bounds__(128) k_cdash_part(const float* __restrict__ cont,
                                                    const int* __restrict__ cmask) {
    __shared__ float es[128];
    __shared__ float red[128];
    int b = blockIdx.x;
    int d0 = blockIdx.y * 128;
    int chunk = blockIdx.z;
    int t = threadIdx.x;

    float xv[4];
    float lm = FLOOR_F;
#pragma unroll
    for (int r = 0; r < 4; r++) {
        int c = t + 128 * r;
        float x = g_Smax[b * CC + c] + (1.0f - (float)cmask[b * CC + c]) * NEGV;
        xv[r] = x;
        lm = fmaxf(lm, x);
    }
    red[t] = lm;
    __syncthreads();
    for (int o = 64; o; o >>= 1) {
        if (t < o) red[t] = fmaxf(red[t], red[t + o]);
        __syncthreads();
    }
    float m = red[0];
    __syncthreads();
    float lsum = 0.f;
#pragma unroll
    for (int r = 0; r < 4; r++) lsum += __expf(xv[r] - m);
    red[t] = lsum;
    __syncthreads();
    for (int o = 64; o; o >>= 1) {
        if (t < o) red[t] += red[t + o];
        __syncthreads();
    }
    float inv = 1.0f / red[0];
    __syncthreads();
    es[t] = __expf(xv[chunk] - m) * inv;
    __syncthreads();

    int d = d0 + t;
    const float* cb = cont + ((size_t)b * CC + (size_t)chunk * 128) * DD + d;
    float a0 = 0.f, a1 = 0.f, a2 = 0.f, a3 = 0.f;
    for (int c = 0; c < 128; c += 4) {
        a0 += es[c + 0] * cb[(size_t)(c + 0) * DD];
        a1 += es[c + 1] * cb[(size_t)(c + 1) * DD];
        a2 += es[c + 2] * cb[(size_t)(c + 2) * DD];
        a3 += es[c + 3] * cb[(size_t)(c + 3) * DD];
    }
    g_cdpart[((size_t)chunk * BB + b) * DD + d] = (a0 + a1) + (a2 + a3);
}

__global__ void k_cdcombine() {
    int i = blockIdx.x * blockDim.x + threadIdx.x;
    if (i >= BB * DD) return;
    g_cdash[i] = (g_cdpart[i] + g_cdpart[BB * DD + i]) +
                 (g_cdpart[2 * BB * DD + i] + g_cdpart[3 * BB * DD + i]);
}

// ---------------- K4: c2q = P @ qT, P persistent across d-tiles ------------
// grid (C/128, B), block 256. Per block: build P once, loop 6 d-tiles.
__global__ void __launch_bounds__(256) k_out_mma(const float* __restrict__ cont,
                                                 const int* __restrict__ qmask,
                                                 float* __restrict__ out) {
    extern __shared__ char sm[];
    uint32_t* Ps = (uint32_t*)sm;                       // [128][132]
    uint32_t* Qs = (uint32_t*)(sm + 128 * 132 * 4);     // [128][132]
    float* cm_s = (float*)(sm + 2 * 128 * 132 * 4);
    float* ci_s = cm_s + 128;
    float* cmt_s = ci_s + 128;
    float* cd_s = cmt_s + 128;

    int t = threadIdx.x;
    int wid = t >> 5, lane = t & 31;
    int gp = lane >> 2, tq = lane & 3;
    int warp_m = wid & 3, warp_n = wid >> 2;
    int mbase = warp_m * 32, nbase = warp_n * 64;
    int b = blockIdx.y;
    int c0 = blockIdx.x * 128;

    if (t < 128) {
        cm_s[t] = g_colmax[b * QQ + t];
        ci_s[t] = g_colinv[b * QQ + t];
        cmt_s[t] = (1.0f - (float)qmask[b * QQ + t]) * NEGV;
    }
    __syncthreads();

    // build P tile once: P = exp((s + cmt) - cm) * ci, tf32
    int lrow = t >> 2, lq4 = (t & 3) * 4;
#pragma unroll
    for (int r = 0; r < 2; r++) {
        int row = lrow + 64 * r;
        const float* Srow = g_S + ((size_t)b * CC + c0 + row) * QQ;
#pragma unroll
        for (int kc = 0; kc < 8; kc++) {
            int col = kc * 16 + lq4;
            float4 s = *(const float4*)(Srow + col);
            float4 mt4 = *(const float4*)(cmt_s + col);
            float4 cm4 = *(const float4*)(cm_s + col);
            float4 ci4 = *(const float4*)(ci_s + col);
            uint4 v;
            v.x = f2tf(__expf((s.x + mt4.x) - cm4.x) * ci4.x);
            v.y = f2tf(__expf((s.y + mt4.y) - cm4.y) * ci4.y);
            v.z = f2tf(__expf((s.z + mt4.z) - cm4.z) * ci4.z);
            v.w = f2tf(__expf((s.w + mt4.w) - cm4.w) * ci4.w);
            *(uint4*)(Ps + row * 132 + col) = v;
        }
    }

    for (int dt = 0; dt < 6; dt++) {
        int d0 = dt * 128;
        if (dt) __syncthreads();
        // load Q tile (d rows x q cols) + cd slice
#pragma unroll
        for (int r = 0; r < 2; r++) {
            int row = lrow + 64 * r;
            const float* qrow = g_qT + ((size_t)b * DD + d0 + row) * QQ;
#pragma unroll
            for (int kc = 0; kc < 8; kc++) {
                int col = kc * 16 + lq4;
                float4 qv = *(const float4*)(qrow + col);
                uint4 v;
                v.x = f2tf(qv.x); v.y = f2tf(qv.y);
                v.z = f2tf(qv.z); v.w = f2tf(qv.w);
                *(uint4*)(Qs + row * 132 + col) = v;
            }
        }
        if (t < 128) cd_s[t] = g_cdash[b * DD + d0 + t];
        __syncthreads();

        float acc[2][8][4];
#pragma unroll
        for (int mt = 0; mt < 2; mt++)
#pragma unroll
            for (int nt = 0; nt < 8; nt++)
#pragma unroll
                for (int j = 0; j < 4; j++) acc[mt][nt][j] = 0.f;

#pragma unroll 4
        for (int ks = 0; ks < 16; ks++) {
            int kk = ks * 8;
            uint32_t aF[2][4];
#pragma unroll
            for (int mt = 0; mt < 2; mt++) {
                int mrow = mbase + mt * 16 + gp;
                aF[mt][0] = Ps[mrow * 132 + kk + tq];
                aF[mt][1] = Ps[(mrow + 8) * 132 + kk + tq];
                aF[mt][2] = Ps[mrow * 132 + kk + tq + 4];
                aF[mt][3] = Ps[(mrow + 8) * 132 + kk + tq + 4];
            }
            uint32_t bF[8][2];
#pragma unroll
            for (int nt = 0; nt < 8; nt++) {
                int nrow = nbase + nt * 8 + gp;
                bF[nt][0] = Qs[nrow * 132 + kk + tq];
                bF[nt][1] = Qs[nrow * 132 + kk + tq + 4];
            }
#pragma unroll
            for (int mt = 0; mt < 2; mt++)
#pragma unroll
                for (int nt = 0; nt < 8; nt++)
                    mma_tf32(acc[mt][nt], aF[mt], bF[nt]);
        }

        // epilogue: out = [c | c2q | c*c2q | c*c_dash]
#pragma unroll
        for (int mt = 0; mt < 2; mt++) {
#pragma unroll
            for (int half = 0; half < 2; half++) {
                int rl = mbase + mt * 16 + gp + half * 8;
                size_t crow = (size_t)b * CC + c0 + rl;
                const float* crp = cont + crow * DD;
                float* orp = out + crow * (4 * DD);
#pragma unroll
                for (int nt = 0; nt < 8; nt++) {
                    int dloc = nbase + nt * 8 + 2 * tq;
                    int dcol = d0 + dloc;
                    float c2q0 = acc[mt][nt][half * 2 + 0];
                    float c2q1 = acc[mt][nt][half * 2 + 1];
                    float2 cv = *(const float2*)(crp + dcol);
                    float cd0 = cd_s[dloc], cd1 = cd_s[dloc + 1];
                    *(float2*)(orp + dcol) = cv;
                    *(float2*)(orp + DD + dcol) = make_float2(c2q0, c2q1);
                    *(float2*)(orp + 2 * DD + dcol) =
                        make_float2(cv.x * c2q0, cv.y * c2q1);
                    *(float2*)(orp + 3 * DD + dcol) =
                        make_float2(cv.x * cd0, cv.y * cd1);
                }
            }
        }
    }
}

// ---------------- launch ---------------------------------------------------
extern "C" void kernel_launch(void* const* d_in, const int* in_sizes, int n_in,
                              void* d_out, int out_size) {
    const float* cont = (const float*)d_in[0];   // (32,512,768) f32
    const int* cmask = (const int*)d_in[1];      // (32,512) i32
    const float* ques = (const float*)d_in[2];   // (32,128,768) f32
    const int* qmask = (const int*)d_in[3];      // (32,128) i32
    const float* SW = (const float*)d_in[4];     // (2304,) f32
    float* out = (float*)d_out;                  // (32,512,3072) f32

    const int OUT_SMEM = 2 * 128 * 132 * 4 + 4 * 128 * 4;  // 137216
    cudaFuncSetAttribute(k_out_mma, cudaFuncAttributeMaxDynamicSharedMemorySize,
                         OUT_SMEM);

    k_rowdots<<<2560, 256>>>(cont, ques, SW);
    k_qtrans<<<dim3(QQ / 32, DD / 32, BB), dim3(32, 8)>>>(ques);
    k_sim_mma<<<dim3(CC / 128, BB), 256>>>(cont, ques, SW, qmask);
    k_colcombine<<<(BB * QQ + 255) / 256, 256>>>();
    k_cdash_part<<<dim3(BB, DD / 128, 4), 128>>>(cont, cmask);
    k_cdcombine<<<(BB * DD + 255) / 256, 256>>>();
    k_out_mma<<<dim3(CC / 128, BB), 256, OUT_SMEM>>>(cont, qmask, out);
}